// round 1
// baseline (speedup 1.0000x reference)
#include <cuda_runtime.h>
#include <math.h>

// Problem constants
#define B_SZ   128
#define K_SZ   256
#define M_SZ   8
#define D_SZ   128
#define NQ     (B_SZ * K_SZ)   // 32768 query rows (b,k)
#define NP     (K_SZ * M_SZ)   // 2048 prototype rows (c,m)

#define GAMMA_F  20.0f
#define LAMBDA_F 20.0f
#define MARGIN_F 0.05f
#define EPS_F    1e-8f

// Tile config
#define BM 128      // query rows per CTA
#define BN 128      // prototype rows per chunk (= 16 concepts)
#define NTHREADS 256

__device__ float g_loss_sum;
__device__ int   g_pos_cnt;

__global__ void mpc_init_kernel() {
    g_loss_sum = 0.0f;
    g_pos_cnt  = 0;
}

__global__ __launch_bounds__(NTHREADS)
void mpc_main_kernel(const float* __restrict__ V,      // [NQ, D]
                     const int*   __restrict__ labels, // [NQ]
                     const float* __restrict__ P)      // [NP, D]
{
    extern __shared__ float smem[];
    float* At = smem;                 // [D][BM] kk-major (transposed A)
    float* Bt = smem + D_SZ * BM;     // [D][BN] kk-major (transposed B)

    const int tid = threadIdx.x;
    const int tx  = tid & 15;         // 0..15 -> concept within chunk
    const int ty  = tid >> 4;         // 0..15 -> row group (8 rows)
    const int rowBase = blockIdx.x * BM;

    // ---- Load A (query tile) transposed into SMEM, once ----
    // Lanes vary over row -> conflict-free STS; gmem reads are strided
    // (2x sector overhead, negligible: A read once).
    {
        const int r  = tid & 127;
        const int c0 = tid >> 7;   // 0 or 1
        const float4* gv = (const float4*)(V + (size_t)(rowBase + r) * D_SZ);
        #pragma unroll
        for (int c4 = 0; c4 < 32; c4 += 2) {
            float4 v = __ldg(gv + (c4 + c0));
            int kk = (c4 + c0) * 4;
            At[(kk + 0) * BM + r] = v.x;
            At[(kk + 1) * BM + r] = v.y;
            At[(kk + 2) * BM + r] = v.z;
            At[(kk + 3) * BM + r] = v.w;
        }
    }

    float denomAcc[8];   // per owned row: sum_c exp(lambda*sim_c) partials
    float simPos[8];     // per owned row: sim at c == k (others contribute 0)
    #pragma unroll
    for (int i = 0; i < 8; i++) { denomAcc[i] = 0.0f; simPos[i] = 0.0f; }

    const int NCHUNK = NP / BN;  // 16
    for (int chunk = 0; chunk < NCHUNK; ++chunk) {
        __syncthreads();   // previous compute done reading Bt
        // ---- Load B chunk transposed ----
        {
            const int r  = tid & 127;
            const int c0 = tid >> 7;
            const float4* gp = (const float4*)(P + (size_t)(chunk * BN + r) * D_SZ);
            #pragma unroll
            for (int c4 = 0; c4 < 32; c4 += 2) {
                float4 v = __ldg(gp + (c4 + c0));
                int kk = (c4 + c0) * 4;
                Bt[(kk + 0) * BN + r] = v.x;
                Bt[(kk + 1) * BN + r] = v.y;
                Bt[(kk + 2) * BN + r] = v.z;
                Bt[(kk + 3) * BN + r] = v.w;
            }
        }
        __syncthreads();

        // ---- 128x128 GEMM tile, 8x8 per thread ----
        float acc[8][8];
        #pragma unroll
        for (int i = 0; i < 8; i++)
            #pragma unroll
            for (int j = 0; j < 8; j++)
                acc[i][j] = 0.0f;

        const float* aBase = At + ty * 8;
        const float* bBase = Bt + tx * 8;
        #pragma unroll 4
        for (int kk = 0; kk < D_SZ; ++kk) {
            float4 a0 = *(const float4*)(aBase + kk * BM);
            float4 a1 = *(const float4*)(aBase + kk * BM + 4);
            float4 b0 = *(const float4*)(bBase + kk * BN);
            float4 b1 = *(const float4*)(bBase + kk * BN + 4);
            float a[8] = {a0.x, a0.y, a0.z, a0.w, a1.x, a1.y, a1.z, a1.w};
            float b[8] = {b0.x, b0.y, b0.z, b0.w, b1.x, b1.y, b1.z, b1.w};
            #pragma unroll
            for (int i = 0; i < 8; i++)
                #pragma unroll
                for (int j = 0; j < 8; j++)
                    acc[i][j] = fmaf(a[i], b[j], acc[i][j]);
        }

        // ---- Fused epilogue: this thread owns concept c for its 8 rows ----
        const int c = chunk * 16 + tx;   // global concept index
        #pragma unroll
        for (int i = 0; i < 8; i++) {
            float mx = acc[i][0];
            #pragma unroll
            for (int j = 1; j < 8; j++) mx = fmaxf(mx, acc[i][j]);
            float Z = 0.0f, W = 0.0f;
            #pragma unroll
            for (int j = 0; j < 8; j++) {
                float e = __expf(GAMMA_F * (acc[i][j] - mx));
                Z += e;
                W += e * acc[i][j];
            }
            float sim = W / Z;                       // softmax-weighted similarity
            denomAcc[i] += __expf(LAMBDA_F * sim);   // contrastive denominator term
            int krow = (rowBase + ty * 8 + i) & (K_SZ - 1);  // k of this row
            if (c == krow) simPos[i] = sim;
        }
    }

    // ---- Reduce denom/simPos across the 16 tx lanes (half-warp) ----
    float lsum = 0.0f;
    int   lcnt = 0;
    #pragma unroll
    for (int i = 0; i < 8; i++) {
        float d = denomAcc[i];
        float p = simPos[i];
        #pragma unroll
        for (int o = 8; o > 0; o >>= 1) {
            d += __shfl_xor_sync(0xffffffffu, d, o);
            p += __shfl_xor_sync(0xffffffffu, p, o);
        }
        if (tx == 0) {
            int row = rowBase + ty * 8 + i;
            float loss = logf(d + EPS_F) - LAMBDA_F * (p + MARGIN_F);
            if (labels[row] == 1) { lsum += loss; lcnt += 1; }
        }
    }

    // ---- CTA reduce + single atomic pair ----
    __shared__ float red_s[16];
    __shared__ int   red_c[16];
    __syncthreads();
    if (tx == 0) { red_s[ty] = lsum; red_c[ty] = lcnt; }
    __syncthreads();
    if (tid == 0) {
        float s = 0.0f; int n = 0;
        #pragma unroll
        for (int i = 0; i < 16; i++) { s += red_s[i]; n += red_c[i]; }
        atomicAdd(&g_loss_sum, s);
        atomicAdd(&g_pos_cnt, n);
    }
}

__global__ void mpc_fin_kernel(float* out) {
    float s = g_loss_sum;
    int   n = g_pos_cnt;
    out[0] = (n > 0) ? (s / (float)n) : s;
}

extern "C" void kernel_launch(void* const* d_in, const int* in_sizes, int n_in,
                              void* d_out, int out_size)
{
    // Map inputs by element count (robust to ordering):
    // v_proj: 128*256*128 = 4194304, labels: 32768, prototypes: 2048*128 = 262144
    const float* V = nullptr;
    const int*   L = nullptr;
    const float* P = nullptr;
    for (int i = 0; i < n_in; i++) {
        if      (in_sizes[i] == NQ * D_SZ) V = (const float*)d_in[i];
        else if (in_sizes[i] == NQ)        L = (const int*)d_in[i];
        else if (in_sizes[i] == NP * D_SZ) P = (const float*)d_in[i];
    }

    const int smemBytes = (D_SZ * BM + D_SZ * BN) * (int)sizeof(float); // 128 KB
    cudaFuncSetAttribute(mpc_main_kernel,
                         cudaFuncAttributeMaxDynamicSharedMemorySize, smemBytes);

    mpc_init_kernel<<<1, 1>>>();
    mpc_main_kernel<<<NQ / BM, NTHREADS, smemBytes>>>(V, L, P);
    mpc_fin_kernel<<<1, 1>>>((float*)d_out);
}

// round 3
// speedup vs baseline: 1.4603x; 1.4603x over previous
#include <cuda_runtime.h>
#include <cuda_bf16.h>
#include <math.h>
#include <stdint.h>

// ---------------- problem constants ----------------
#define B_SZ   128
#define K_SZ   256
#define M_SZ   8
#define D_SZ   128
#define NQ     (B_SZ * K_SZ)   // 32768 query rows
#define NP     (K_SZ * M_SZ)   // 2048 prototype rows

#define GAMMA_F  20.0f
#define LAMBDA_F 20.0f
#define MARGIN_F 0.05f
#define EPS_F    1e-8f

// ---------------- tile config ----------------
#define BM 256              // query rows per CTA (full K: k == row)
#define BN 128              // prototype rows per chunk (16 concepts)
#define NCHUNK (NP / BN)    // 16
#define NTHREADS 512        // 16 warps: warp_m = w>>2 (4), warp_n = w&3 (4)

// padded bf16 tile row stride: 128 + 8 elems -> 272 bytes (conflict-free ldmatrix/STS)
#define TSTRIDE 272

#define OFF_A_HI 0
#define OFF_A_LO (BM * TSTRIDE)                 // 69632
#define OFF_B_HI (2 * BM * TSTRIDE)             // 139264
#define OFF_B_LO (2 * BM * TSTRIDE + BN * TSTRIDE)   // 174080
#define OFF_RED  (2 * BM * TSTRIDE + 2 * BN * TSTRIDE) // 208896
#define SMEM_BYTES (OFF_RED + 2 * BM * 4)       // + denom[256] + sims[256]

__device__ float g_loss_sum;
__device__ int   g_pos_cnt;

__device__ __forceinline__ uint32_t smem_u32(const void* p) {
    uint32_t a;
    asm("{ .reg .u64 t; cvta.to.shared.u64 t, %1; cvt.u32.u64 %0, t; }" : "=r"(a) : "l"(p));
    return a;
}

__device__ __forceinline__ void ldsm_x4(uint32_t& r0, uint32_t& r1, uint32_t& r2, uint32_t& r3,
                                        uint32_t addr) {
    asm volatile("ldmatrix.sync.aligned.m8n8.x4.shared.b16 {%0,%1,%2,%3}, [%4];"
                 : "=r"(r0), "=r"(r1), "=r"(r2), "=r"(r3) : "r"(addr));
}

__device__ __forceinline__ void mma_bf16(float* c, uint32_t a0, uint32_t a1, uint32_t a2,
                                         uint32_t a3, uint32_t b0, uint32_t b1) {
    asm volatile(
        "mma.sync.aligned.m16n8k16.row.col.f32.bf16.bf16.f32 "
        "{%0,%1,%2,%3}, {%4,%5,%6,%7}, {%8,%9}, {%0,%1,%2,%3};"
        : "+f"(c[0]), "+f"(c[1]), "+f"(c[2]), "+f"(c[3])
        : "r"(a0), "r"(a1), "r"(a2), "r"(a3), "r"(b0), "r"(b1));
}

__device__ __forceinline__ uint32_t pack2(float a, float b) {
    __nv_bfloat162 t = __floats2bfloat162_rn(a, b);
    return *reinterpret_cast<uint32_t*>(&t);
}

// Load ROWS x 128 fp32 tile from gmem, split each value into bf16 hi + bf16 lo
// (residual), store into padded row-major bf16 tiles (stride TSTRIDE bytes).
template <int ROWS>
__device__ __forceinline__ void load_split(const float* __restrict__ src,
                                           char* hi, char* lo, int tid) {
    constexpr int ITER = ROWS * 32 / NTHREADS;   // float4 per thread
    #pragma unroll
    for (int i = 0; i < ITER; i++) {
        int linear = tid + i * NTHREADS;
        int row  = linear >> 5;
        int col4 = linear & 31;                  // float4 index within row
        float4 v = __ldg(reinterpret_cast<const float4*>(src) + linear);

        float hx = __bfloat162float(__float2bfloat16(v.x));
        float hy = __bfloat162float(__float2bfloat16(v.y));
        float hz = __bfloat162float(__float2bfloat16(v.z));
        float hw = __bfloat162float(__float2bfloat16(v.w));

        uint32_t addr = (uint32_t)row * TSTRIDE + (uint32_t)col4 * 8;
        *reinterpret_cast<uint2*>(hi + addr) = make_uint2(pack2(hx, hy), pack2(hz, hw));
        *reinterpret_cast<uint2*>(lo + addr) =
            make_uint2(pack2(v.x - hx, v.y - hy), pack2(v.z - hz, v.w - hw));
    }
}

__global__ void mpc_init_kernel() {
    g_loss_sum = 0.0f;
    g_pos_cnt  = 0;
}

__global__ __launch_bounds__(NTHREADS, 1)
void mpc_main_kernel(const float* __restrict__ V,
                     const int*   __restrict__ labels,
                     const float* __restrict__ P)
{
    extern __shared__ char smem[];
    const uint32_t sb = smem_u32(smem);
    const int tid  = threadIdx.x;
    const int warp = tid >> 5;
    const int lane = tid & 31;
    const int warp_m = warp >> 2;   // 0..3 -> rows 64*warp_m
    const int warp_n = warp & 3;    // 0..3 -> cols 32*warp_n
    const int rowBase = blockIdx.x * BM;

    float* denom_s = reinterpret_cast<float*>(smem + OFF_RED);
    float* sims_s  = denom_s + BM;

    if (tid < BM) { denom_s[tid] = 0.0f; sims_s[tid] = 0.0f; }

    // resident A tile (this CTA's 256 query rows), hi/lo split
    load_split<BM>(V + (size_t)rowBase * D_SZ, smem + OFF_A_HI, smem + OFF_A_LO, tid);

    // lane-invariant parts of ldmatrix addresses
    // A x4: lanes 0-15 rows 0-15 khalf0, lanes 16-31 rows 0-15 khalf1
    const uint32_t aLane = (uint32_t)(warp_m * 64 + (lane & 15)) * TSTRIDE
                         + (uint32_t)(lane >> 4) * 16;
    // B x4: m0/m1 = n 0-7 (khalf 0/1), m2/m3 = n 8-15 (khalf 0/1)
    const uint32_t bLane = (uint32_t)(warp_n * 32 + ((lane >> 4) << 3) + (lane & 7)) * TSTRIDE
                         + (uint32_t)((lane >> 3) & 1) * 16;

    float denomAcc[8], simPos[8];
    #pragma unroll
    for (int i = 0; i < 8; i++) { denomAcc[i] = 0.0f; simPos[i] = 0.0f; }

    for (int chunk = 0; chunk < NCHUNK; ++chunk) {
        __syncthreads();   // previous compute finished reading B (also covers A stores, iter 0)
        load_split<BN>(P + (size_t)(chunk * BN) * D_SZ, smem + OFF_B_HI, smem + OFF_B_LO, tid);
        __syncthreads();

        float acc[4][4][4];
        #pragma unroll
        for (int mf = 0; mf < 4; mf++)
            #pragma unroll
            for (int nf = 0; nf < 4; nf++)
                #pragma unroll
                for (int q = 0; q < 4; q++)
                    acc[mf][nf][q] = 0.0f;

        // 3 bf16 passes: Ahi*Bhi, Alo*Bhi, Ahi*Blo
        #pragma unroll
        for (int pass = 0; pass < 3; ++pass) {
            const uint32_t aBase = sb + (pass == 1 ? OFF_A_LO : OFF_A_HI) + aLane;
            const uint32_t bBase = sb + (pass == 2 ? OFF_B_LO : OFF_B_HI) + bLane;
            #pragma unroll
            for (int ks = 0; ks < 8; ++ks) {
                uint32_t a[4][4];
                #pragma unroll
                for (int mf = 0; mf < 4; mf++)
                    ldsm_x4(a[mf][0], a[mf][1], a[mf][2], a[mf][3],
                            aBase + (uint32_t)(mf * 16) * TSTRIDE + (uint32_t)ks * 32);
                #pragma unroll
                for (int np = 0; np < 2; np++) {
                    uint32_t b0, b1, b2, b3;   // (b0,b1)=nfrag 2*np, (b2,b3)=nfrag 2*np+1
                    ldsm_x4(b0, b1, b2, b3,
                            bBase + (uint32_t)(np * 16) * TSTRIDE + (uint32_t)ks * 32);
                    #pragma unroll
                    for (int mf = 0; mf < 4; mf++) {
                        mma_bf16(acc[mf][2 * np],     a[mf][0], a[mf][1], a[mf][2], a[mf][3], b0, b1);
                        mma_bf16(acc[mf][2 * np + 1], a[mf][0], a[mf][1], a[mf][2], a[mf][3], b2, b3);
                    }
                }
            }
        }

        // ---- fused epilogue on fragments ----
        // thread quad (lanes with same lane>>2) spans 8 cols = one concept's prototypes
        #pragma unroll
        for (int mf = 0; mf < 4; ++mf) {
            const int rl = warp_m * 64 + mf * 16 + (lane >> 2);   // low row (high = rl+8)
            #pragma unroll
            for (int nf = 0; nf < 4; ++nf) {
                float c0 = acc[mf][nf][0], c1 = acc[mf][nf][1];
                float c2 = acc[mf][nf][2], c3 = acc[mf][nf][3];
                float e0 = __expf(GAMMA_F * c0), e1 = __expf(GAMMA_F * c1);
                float e2 = __expf(GAMMA_F * c2), e3 = __expf(GAMMA_F * c3);
                float Zl = e0 + e1, Wl = fmaf(e0, c0, e1 * c1);
                float Zh = e2 + e3, Wh = fmaf(e2, c2, e3 * c3);
                #pragma unroll
                for (int o = 1; o <= 2; o <<= 1) {
                    Zl += __shfl_xor_sync(0xffffffffu, Zl, o);
                    Wl += __shfl_xor_sync(0xffffffffu, Wl, o);
                    Zh += __shfl_xor_sync(0xffffffffu, Zh, o);
                    Wh += __shfl_xor_sync(0xffffffffu, Wh, o);
                }
                if ((lane & 3) == 0) {
                    float sl = Wl / Zl;
                    float sh = Wh / Zh;
                    denomAcc[2 * mf]     += __expf(LAMBDA_F * sl);
                    denomAcc[2 * mf + 1] += __expf(LAMBDA_F * sh);
                    int cg = chunk * 16 + warp_n * 4 + nf;   // global concept
                    if (cg == rl)     simPos[2 * mf]     = sl;   // k == row (BM==K_SZ)
                    if (cg == rl + 8) simPos[2 * mf + 1] = sh;
                }
            }
        }
    }

    // ---- per-row combine across warp_n via smem atomics ----
    __syncthreads();
    if ((lane & 3) == 0) {
        #pragma unroll
        for (int mf = 0; mf < 4; ++mf) {
            int r = warp_m * 64 + mf * 16 + (lane >> 2);
            atomicAdd(&denom_s[r],     denomAcc[2 * mf]);
            atomicAdd(&denom_s[r + 8], denomAcc[2 * mf + 1]);
            atomicAdd(&sims_s[r],      simPos[2 * mf]);
            atomicAdd(&sims_s[r + 8],  simPos[2 * mf + 1]);
        }
    }
    __syncthreads();

    float lsum = 0.0f;
    int   lcnt = 0;
    if (tid < BM) {
        float d = denom_s[tid];
        float p = sims_s[tid];
        float loss = logf(d + EPS_F) - LAMBDA_F * (p + MARGIN_F);
        if (labels[rowBase + tid] == 1) { lsum = loss; lcnt = 1; }
    }
    #pragma unroll
    for (int o = 16; o > 0; o >>= 1) {
        lsum += __shfl_xor_sync(0xffffffffu, lsum, o);
        lcnt += __shfl_xor_sync(0xffffffffu, lcnt, o);
    }
    __shared__ float ws[16];
    __shared__ int   wc[16];
    if (lane == 0) { ws[warp] = lsum; wc[warp] = lcnt; }
    __syncthreads();
    if (tid == 0) {
        float s = 0.0f; int n = 0;
        #pragma unroll
        for (int i = 0; i < 16; i++) { s += ws[i]; n += wc[i]; }
        atomicAdd(&g_loss_sum, s);
        atomicAdd(&g_pos_cnt, n);
    }
}

__global__ void mpc_fin_kernel(float* out) {
    float s = g_loss_sum;
    int   n = g_pos_cnt;
    out[0] = (n > 0) ? (s / (float)n) : s;
}

extern "C" void kernel_launch(void* const* d_in, const int* in_sizes, int n_in,
                              void* d_out, int out_size)
{
    const float* V = nullptr;
    const int*   L = nullptr;
    const float* P = nullptr;
    for (int i = 0; i < n_in; i++) {
        if      (in_sizes[i] == NQ * D_SZ) V = (const float*)d_in[i];
        else if (in_sizes[i] == NQ)        L = (const int*)d_in[i];
        else if (in_sizes[i] == NP * D_SZ) P = (const float*)d_in[i];
    }

    cudaFuncSetAttribute(mpc_main_kernel,
                         cudaFuncAttributeMaxDynamicSharedMemorySize, SMEM_BYTES);

    mpc_init_kernel<<<1, 1>>>();
    mpc_main_kernel<<<NQ / BM, NTHREADS, SMEM_BYTES>>>(V, L, P);
    mpc_fin_kernel<<<1, 1>>>((float*)d_out);
}

// round 4
// speedup vs baseline: 1.4746x; 1.0098x over previous
#include <cuda_runtime.h>
#include <cuda_bf16.h>
#include <math.h>
#include <stdint.h>

// ---------------- problem constants ----------------
#define B_SZ   128
#define K_SZ   256
#define M_SZ   8
#define D_SZ   128
#define NQ     (B_SZ * K_SZ)   // 32768 query rows
#define NP     (K_SZ * M_SZ)   // 2048 prototype rows

#define GAMMA_F  20.0f
#define LAMBDA_F 20.0f
#define MARGIN_F 0.05f
#define EPS_F    1e-8f

// ---------------- tile config ----------------
#define BM 256              // query rows per CTA (full K: k == row)
#define BN 128              // prototype rows per chunk (16 concepts)
#define NCHUNK (NP / BN)    // 16
#define NTHREADS 512        // 16 warps: warp_m = w>>2 (4), warp_n = w&3 (4)
#define NCTAS (NQ / BM)     // 128

// padded bf16 tile row stride: 128 + 8 elems -> 272 bytes (conflict-free ldmatrix/STS)
#define TSTRIDE 272

#define OFF_A_HI 0
#define OFF_A_LO (BM * TSTRIDE)
#define OFF_B_HI (2 * BM * TSTRIDE)
#define OFF_B_LO (2 * BM * TSTRIDE + BN * TSTRIDE)
#define OFF_RED  (2 * BM * TSTRIDE + 2 * BN * TSTRIDE)
#define SMEM_BYTES (OFF_RED + 2 * BM * 4)

__device__ float g_loss_sum;   // zero-initialized at load; reset by last CTA
__device__ int   g_pos_cnt;
__device__ unsigned int g_done;

__device__ __forceinline__ uint32_t smem_u32(const void* p) {
    uint32_t a;
    asm("{ .reg .u64 t; cvta.to.shared.u64 t, %1; cvt.u32.u64 %0, t; }" : "=r"(a) : "l"(p));
    return a;
}

__device__ __forceinline__ void ldsm_x4(uint32_t& r0, uint32_t& r1, uint32_t& r2, uint32_t& r3,
                                        uint32_t addr) {
    asm volatile("ldmatrix.sync.aligned.m8n8.x4.shared.b16 {%0,%1,%2,%3}, [%4];"
                 : "=r"(r0), "=r"(r1), "=r"(r2), "=r"(r3) : "r"(addr));
}

__device__ __forceinline__ void mma_bf16(float* c, uint32_t a0, uint32_t a1, uint32_t a2,
                                         uint32_t a3, uint32_t b0, uint32_t b1) {
    asm volatile(
        "mma.sync.aligned.m16n8k16.row.col.f32.bf16.bf16.f32 "
        "{%0,%1,%2,%3}, {%4,%5,%6,%7}, {%8,%9}, {%0,%1,%2,%3};"
        : "+f"(c[0]), "+f"(c[1]), "+f"(c[2]), "+f"(c[3])
        : "r"(a0), "r"(a1), "r"(a2), "r"(a3), "r"(b0), "r"(b1));
}

__device__ __forceinline__ uint32_t pack2(float a, float b) {
    __nv_bfloat162 t = __floats2bfloat162_rn(a, b);
    return *reinterpret_cast<uint32_t*>(&t);
}

// Load ROWS x 128 fp32 tile from gmem, split each value into bf16 hi + bf16 lo
// (residual), store into padded row-major bf16 tiles (stride TSTRIDE bytes).
template <int ROWS>
__device__ __forceinline__ void load_split(const float* __restrict__ src,
                                           char* hi, char* lo, int tid) {
    constexpr int ITER = ROWS * 32 / NTHREADS;
    #pragma unroll
    for (int i = 0; i < ITER; i++) {
        int linear = tid + i * NTHREADS;
        int row  = linear >> 5;
        int col4 = linear & 31;
        float4 v = __ldg(reinterpret_cast<const float4*>(src) + linear);

        float hx = __bfloat162float(__float2bfloat16(v.x));
        float hy = __bfloat162float(__float2bfloat16(v.y));
        float hz = __bfloat162float(__float2bfloat16(v.z));
        float hw = __bfloat162float(__float2bfloat16(v.w));

        uint32_t addr = (uint32_t)row * TSTRIDE + (uint32_t)col4 * 8;
        *reinterpret_cast<uint2*>(hi + addr) = make_uint2(pack2(hx, hy), pack2(hz, hw));
        *reinterpret_cast<uint2*>(lo + addr) =
            make_uint2(pack2(v.x - hx, v.y - hy), pack2(v.z - hz, v.w - hw));
    }
}

__global__ __launch_bounds__(NTHREADS, 1)
void mpc_main_kernel(const float* __restrict__ V,
                     const int*   __restrict__ labels,
                     const float* __restrict__ P,
                     float* __restrict__ out)
{
    extern __shared__ char smem[];
    const uint32_t sb = smem_u32(smem);
    const int tid  = threadIdx.x;
    const int warp = tid >> 5;
    const int lane = tid & 31;
    const int warp_m = warp >> 2;   // 0..3 -> rows 64*warp_m
    const int warp_n = warp & 3;    // 0..3 -> cols 32*warp_n
    const int rowBase = blockIdx.x * BM;

    float* denom_s = reinterpret_cast<float*>(smem + OFF_RED);
    float* sims_s  = denom_s + BM;

    if (tid < BM) { denom_s[tid] = 0.0f; sims_s[tid] = 0.0f; }

    // resident A tile (this CTA's 256 query rows), hi/lo split
    load_split<BM>(V + (size_t)rowBase * D_SZ, smem + OFF_A_HI, smem + OFF_A_LO, tid);

    // lane-invariant ldmatrix address components
    const uint32_t aLane = (uint32_t)(warp_m * 64 + (lane & 15)) * TSTRIDE
                         + (uint32_t)(lane >> 4) * 16;
    const uint32_t bLane = (uint32_t)(warp_n * 32 + ((lane >> 4) << 3) + (lane & 7)) * TSTRIDE
                         + (uint32_t)((lane >> 3) & 1) * 16;

    float denomAcc[8], simPos[8];
    #pragma unroll
    for (int i = 0; i < 8; i++) { denomAcc[i] = 0.0f; simPos[i] = 0.0f; }

    for (int chunk = 0; chunk < NCHUNK; ++chunk) {
        __syncthreads();
        load_split<BN>(P + (size_t)(chunk * BN) * D_SZ, smem + OFF_B_HI, smem + OFF_B_LO, tid);
        __syncthreads();

        // two sequential 16-column halves -> acc fits in 32 regs (no spills)
        #pragma unroll
        for (int h = 0; h < 2; ++h) {
            float acc[4][2][4];
            #pragma unroll
            for (int mf = 0; mf < 4; mf++)
                #pragma unroll
                for (int nf = 0; nf < 2; nf++)
                    #pragma unroll
                    for (int q = 0; q < 4; q++)
                        acc[mf][nf][q] = 0.0f;

            // 3 bf16 passes: Ahi*Bhi, Alo*Bhi, Ahi*Blo
            #pragma unroll
            for (int pass = 0; pass < 3; ++pass) {
                const uint32_t aBase = sb + (pass == 1 ? OFF_A_LO : OFF_A_HI) + aLane;
                const uint32_t bBase = sb + (pass == 2 ? OFF_B_LO : OFF_B_HI) + bLane
                                     + (uint32_t)(h * 16) * TSTRIDE;
                #pragma unroll
                for (int ks = 0; ks < 8; ++ks) {
                    uint32_t b0, b1, b2, b3;
                    ldsm_x4(b0, b1, b2, b3, bBase + (uint32_t)ks * 32);
                    #pragma unroll
                    for (int mf = 0; mf < 4; mf++) {
                        uint32_t a0, a1, a2, a3;
                        ldsm_x4(a0, a1, a2, a3,
                                aBase + (uint32_t)(mf * 16) * TSTRIDE + (uint32_t)ks * 32);
                        mma_bf16(acc[mf][0], a0, a1, a2, a3, b0, b1);
                        mma_bf16(acc[mf][1], a0, a1, a2, a3, b2, b3);
                    }
                }
            }

            // ---- fused epilogue: quad (lane>>2 fixed) spans one concept's 8 protos ----
            #pragma unroll
            for (int mf = 0; mf < 4; ++mf) {
                const int rl = warp_m * 64 + mf * 16 + (lane >> 2);   // low row
                #pragma unroll
                for (int nf = 0; nf < 2; ++nf) {
                    float c0 = acc[mf][nf][0], c1 = acc[mf][nf][1];
                    float c2 = acc[mf][nf][2], c3 = acc[mf][nf][3];
                    float e0 = __expf(GAMMA_F * c0), e1 = __expf(GAMMA_F * c1);
                    float e2 = __expf(GAMMA_F * c2), e3 = __expf(GAMMA_F * c3);
                    float Zl = e0 + e1, Wl = fmaf(e0, c0, e1 * c1);
                    float Zh = e2 + e3, Wh = fmaf(e2, c2, e3 * c3);
                    #pragma unroll
                    for (int o = 1; o <= 2; o <<= 1) {
                        Zl += __shfl_xor_sync(0xffffffffu, Zl, o);
                        Wl += __shfl_xor_sync(0xffffffffu, Wl, o);
                        Zh += __shfl_xor_sync(0xffffffffu, Zh, o);
                        Wh += __shfl_xor_sync(0xffffffffu, Wh, o);
                    }
                    if ((lane & 3) == 0) {
                        float sl = Wl / Zl;
                        float sh = Wh / Zh;
                        denomAcc[2 * mf]     += __expf(LAMBDA_F * sl);
                        denomAcc[2 * mf + 1] += __expf(LAMBDA_F * sh);
                        int cg = chunk * 16 + warp_n * 4 + h * 2 + nf;   // global concept
                        if (cg == rl)     simPos[2 * mf]     = sl;       // k == row (BM==K_SZ)
                        if (cg == rl + 8) simPos[2 * mf + 1] = sh;
                    }
                }
            }
        }
    }

    // ---- per-row combine across warp_n via smem atomics ----
    __syncthreads();
    if ((lane & 3) == 0) {
        #pragma unroll
        for (int mf = 0; mf < 4; ++mf) {
            int r = warp_m * 64 + mf * 16 + (lane >> 2);
            atomicAdd(&denom_s[r],     denomAcc[2 * mf]);
            atomicAdd(&denom_s[r + 8], denomAcc[2 * mf + 1]);
            atomicAdd(&sims_s[r],      simPos[2 * mf]);
            atomicAdd(&sims_s[r + 8],  simPos[2 * mf + 1]);
        }
    }
    __syncthreads();

    float lsum = 0.0f;
    int   lcnt = 0;
    if (tid < BM) {
        float d = denom_s[tid];
        float p = sims_s[tid];
        float loss = logf(d + EPS_F) - LAMBDA_F * (p + MARGIN_F);
        if (labels[rowBase + tid] == 1) { lsum = loss; lcnt = 1; }
    }
    #pragma unroll
    for (int o = 16; o > 0; o >>= 1) {
        lsum += __shfl_xor_sync(0xffffffffu, lsum, o);
        lcnt += __shfl_xor_sync(0xffffffffu, lcnt, o);
    }
    __shared__ float ws[16];
    __shared__ int   wc[16];
    if (lane == 0) { ws[warp] = lsum; wc[warp] = lcnt; }
    __syncthreads();

    // ---- single-launch finalize: last CTA reduces globals, writes out, resets ----
    if (tid == 0) {
        float s = 0.0f; int n = 0;
        #pragma unroll
        for (int i = 0; i < 16; i++) { s += ws[i]; n += wc[i]; }
        atomicAdd(&g_loss_sum, s);
        atomicAdd(&g_pos_cnt, n);
        __threadfence();
        unsigned int old = atomicAdd(&g_done, 1u);
        if (old == NCTAS - 1) {
            float ts = g_loss_sum;
            int   tn = g_pos_cnt;
            out[0] = (tn > 0) ? (ts / (float)tn) : ts;
            // reset for the next (graph-replayed) call
            g_loss_sum = 0.0f;
            g_pos_cnt  = 0;
            __threadfence();
            g_done = 0u;
        }
    }
}

extern "C" void kernel_launch(void* const* d_in, const int* in_sizes, int n_in,
                              void* d_out, int out_size)
{
    const float* V = nullptr;
    const int*   L = nullptr;
    const float* P = nullptr;
    for (int i = 0; i < n_in; i++) {
        if      (in_sizes[i] == NQ * D_SZ) V = (const float*)d_in[i];
        else if (in_sizes[i] == NQ)        L = (const int*)d_in[i];
        else if (in_sizes[i] == NP * D_SZ) P = (const float*)d_in[i];
    }

    cudaFuncSetAttribute(mpc_main_kernel,
                         cudaFuncAttributeMaxDynamicSharedMemorySize, SMEM_BYTES);

    mpc_main_kernel<<<NCTAS, NTHREADS, SMEM_BYTES>>>(V, L, P, (float*)d_out);
}

// round 5
// speedup vs baseline: 2.5784x; 1.7485x over previous
#include <cuda_runtime.h>
#include <cuda_bf16.h>
#include <math.h>
#include <stdint.h>

// ---------------- problem constants ----------------
#define B_SZ   128
#define K_SZ   256
#define M_SZ   8
#define D_SZ   128
#define NQ     (B_SZ * K_SZ)   // 32768 query rows
#define NP     (K_SZ * M_SZ)   // 2048 prototype rows

#define GAMMA_F  20.0f
#define LAMBDA_F 20.0f
#define MARGIN_F 0.05f
#define EPS_F    1e-8f

// ---------------- tile config ----------------
#define BM 256              // query rows per CTA (full K: k == row-in-CTA)
#define BN 128              // prototype rows per chunk (16 concepts)
#define NCHUNK (NP / BN)    // 16
#define NTHREADS 1024       // 32 warps: warp_m = w>>2 (8), warp_n = w&3 (4)
#define NCTAS (NQ / BM)     // 128

// padded bf16 tile row stride: 128 + 8 elems -> 272 bytes (conflict-free ldmatrix/STS)
#define TSTRIDE 272

#define OFF_A_HI 0
#define OFF_A_LO (BM * TSTRIDE)
#define OFF_B_HI (2 * BM * TSTRIDE)
#define OFF_B_LO (2 * BM * TSTRIDE + BN * TSTRIDE)
#define OFF_RED  (2 * BM * TSTRIDE + 2 * BN * TSTRIDE)
#define SMEM_BYTES (OFF_RED + 2 * BM * 4)

__device__ float g_loss_sum;   // zero-init at load; reset by last CTA each call
__device__ int   g_pos_cnt;
__device__ unsigned int g_done;

__device__ __forceinline__ uint32_t smem_u32(const void* p) {
    uint32_t a;
    asm("{ .reg .u64 t; cvta.to.shared.u64 t, %1; cvt.u32.u64 %0, t; }" : "=r"(a) : "l"(p));
    return a;
}

__device__ __forceinline__ void ldsm_x4(uint32_t& r0, uint32_t& r1, uint32_t& r2, uint32_t& r3,
                                        uint32_t addr) {
    asm volatile("ldmatrix.sync.aligned.m8n8.x4.shared.b16 {%0,%1,%2,%3}, [%4];"
                 : "=r"(r0), "=r"(r1), "=r"(r2), "=r"(r3) : "r"(addr));
}

__device__ __forceinline__ void mma_bf16(float* c, uint32_t a0, uint32_t a1, uint32_t a2,
                                         uint32_t a3, uint32_t b0, uint32_t b1) {
    asm volatile(
        "mma.sync.aligned.m16n8k16.row.col.f32.bf16.bf16.f32 "
        "{%0,%1,%2,%3}, {%4,%5,%6,%7}, {%8,%9}, {%0,%1,%2,%3};"
        : "+f"(c[0]), "+f"(c[1]), "+f"(c[2]), "+f"(c[3])
        : "r"(a0), "r"(a1), "r"(a2), "r"(a3), "r"(b0), "r"(b1));
}

__device__ __forceinline__ uint32_t pack2(float a, float b) {
    __nv_bfloat162 t = __floats2bfloat162_rn(a, b);
    return *reinterpret_cast<uint32_t*>(&t);
}

// Load ROWS x 128 fp32 tile from gmem, split into bf16 hi + residual lo,
// store into padded row-major bf16 tiles (stride TSTRIDE bytes).
template <int ROWS>
__device__ __forceinline__ void load_split(const float* __restrict__ src,
                                           char* hi, char* lo, int tid) {
    constexpr int ITER = ROWS * 32 / NTHREADS;
    #pragma unroll
    for (int i = 0; i < ITER; i++) {
        int linear = tid + i * NTHREADS;
        int row  = linear >> 5;
        int col4 = linear & 31;
        float4 v = __ldg(reinterpret_cast<const float4*>(src) + linear);

        float hx = __bfloat162float(__float2bfloat16(v.x));
        float hy = __bfloat162float(__float2bfloat16(v.y));
        float hz = __bfloat162float(__float2bfloat16(v.z));
        float hw = __bfloat162float(__float2bfloat16(v.w));

        uint32_t addr = (uint32_t)row * TSTRIDE + (uint32_t)col4 * 8;
        *reinterpret_cast<uint2*>(hi + addr) = make_uint2(pack2(hx, hy), pack2(hz, hw));
        *reinterpret_cast<uint2*>(lo + addr) =
            make_uint2(pack2(v.x - hx, v.y - hy), pack2(v.z - hz, v.w - hw));
    }
}

__global__ __launch_bounds__(NTHREADS, 1)
void mpc_main_kernel(const float* __restrict__ V,
                     const int*   __restrict__ labels,
                     const float* __restrict__ P,
                     float* __restrict__ out)
{
    extern __shared__ char smem[];
    const uint32_t sb = smem_u32(smem);
    const int tid  = threadIdx.x;
    const int warp = tid >> 5;
    const int lane = tid & 31;
    const int warp_m = warp >> 2;   // 0..7 -> rows 32*warp_m
    const int warp_n = warp & 3;    // 0..3 -> cols 32*warp_n
    const int rowBase = blockIdx.x * BM;

    float* denom_s = reinterpret_cast<float*>(smem + OFF_RED);
    float* sims_s  = denom_s + BM;

    if (tid < BM) { denom_s[tid] = 0.0f; sims_s[tid] = 0.0f; }

    // resident A tile (this CTA's 256 query rows), hi/lo split
    load_split<BM>(V + (size_t)rowBase * D_SZ, smem + OFF_A_HI, smem + OFF_A_LO, tid);

    // lane-invariant ldmatrix address components
    // A x4: 16 rows (mf half added in loop) x k16; lanes 0-15 khalf0, 16-31 khalf1
    const uint32_t aLane = (uint32_t)(warp_m * 32 + (lane & 15)) * TSTRIDE
                         + (uint32_t)(lane >> 4) * 16;
    // B x4: (b0,b1)=nf0 khalf0/1, (b2,b3)=nf1 khalf0/1 (h half added in loop)
    const uint32_t bLane = (uint32_t)(warp_n * 32 + ((lane >> 4) << 3) + (lane & 7)) * TSTRIDE
                         + (uint32_t)((lane >> 3) & 1) * 16;

    float denomAcc[4], simPos[4];   // [mf*2 + lowhigh]
    #pragma unroll
    for (int i = 0; i < 4; i++) { denomAcc[i] = 0.0f; simPos[i] = 0.0f; }

    for (int chunk = 0; chunk < NCHUNK; ++chunk) {
        __syncthreads();
        load_split<BN>(P + (size_t)(chunk * BN) * D_SZ, smem + OFF_B_HI, smem + OFF_B_LO, tid);
        __syncthreads();

        // two sequential 16-col halves of the 32-col warp tile
        #pragma unroll
        for (int h = 0; h < 2; ++h) {
            float acc[2][2][4];
            #pragma unroll
            for (int mf = 0; mf < 2; mf++)
                #pragma unroll
                for (int nf = 0; nf < 2; nf++)
                    #pragma unroll
                    for (int q = 0; q < 4; q++)
                        acc[mf][nf][q] = 0.0f;

            const uint32_t aHiB = sb + OFF_A_HI + aLane;
            const uint32_t aLoB = sb + OFF_A_LO + aLane;
            const uint32_t bHiB = sb + OFF_B_HI + bLane + (uint32_t)(h * 16) * TSTRIDE;
            const uint32_t bLoB = sb + OFF_B_LO + bLane + (uint32_t)(h * 16) * TSTRIDE;

            // per k-step: load all frags once, issue all 12 MMAs (3 bf16 passes)
            #pragma unroll
            for (int ks = 0; ks < 8; ++ks) {
                const uint32_t ko = (uint32_t)ks * 32;
                uint32_t ah[2][4], al[2][4];
                #pragma unroll
                for (int mf = 0; mf < 2; mf++) {
                    ldsm_x4(ah[mf][0], ah[mf][1], ah[mf][2], ah[mf][3],
                            aHiB + (uint32_t)(mf * 16) * TSTRIDE + ko);
                    ldsm_x4(al[mf][0], al[mf][1], al[mf][2], al[mf][3],
                            aLoB + (uint32_t)(mf * 16) * TSTRIDE + ko);
                }
                uint32_t bh0, bh1, bh2, bh3, bl0, bl1, bl2, bl3;
                ldsm_x4(bh0, bh1, bh2, bh3, bHiB + ko);
                ldsm_x4(bl0, bl1, bl2, bl3, bLoB + ko);

                #pragma unroll
                for (int mf = 0; mf < 2; mf++) {
                    // Ahi*Bhi
                    mma_bf16(acc[mf][0], ah[mf][0], ah[mf][1], ah[mf][2], ah[mf][3], bh0, bh1);
                    mma_bf16(acc[mf][1], ah[mf][0], ah[mf][1], ah[mf][2], ah[mf][3], bh2, bh3);
                    // Alo*Bhi
                    mma_bf16(acc[mf][0], al[mf][0], al[mf][1], al[mf][2], al[mf][3], bh0, bh1);
                    mma_bf16(acc[mf][1], al[mf][0], al[mf][1], al[mf][2], al[mf][3], bh2, bh3);
                    // Ahi*Blo
                    mma_bf16(acc[mf][0], ah[mf][0], ah[mf][1], ah[mf][2], ah[mf][3], bl0, bl1);
                    mma_bf16(acc[mf][1], ah[mf][0], ah[mf][1], ah[mf][2], ah[mf][3], bl2, bl3);
                }
            }

            // ---- fused epilogue: quad spans one concept's 8 prototypes ----
            #pragma unroll
            for (int mf = 0; mf < 2; ++mf) {
                const int rl = warp_m * 32 + mf * 16 + (lane >> 2);   // low row
                #pragma unroll
                for (int nf = 0; nf < 2; ++nf) {
                    float c0 = acc[mf][nf][0], c1 = acc[mf][nf][1];
                    float c2 = acc[mf][nf][2], c3 = acc[mf][nf][3];
                    float e0 = __expf(GAMMA_F * c0), e1 = __expf(GAMMA_F * c1);
                    float e2 = __expf(GAMMA_F * c2), e3 = __expf(GAMMA_F * c3);
                    float Zl = e0 + e1, Wl = fmaf(e0, c0, e1 * c1);
                    float Zh = e2 + e3, Wh = fmaf(e2, c2, e3 * c3);
                    #pragma unroll
                    for (int o = 1; o <= 2; o <<= 1) {
                        Zl += __shfl_xor_sync(0xffffffffu, Zl, o);
                        Wl += __shfl_xor_sync(0xffffffffu, Wl, o);
                        Zh += __shfl_xor_sync(0xffffffffu, Zh, o);
                        Wh += __shfl_xor_sync(0xffffffffu, Wh, o);
                    }
                    if ((lane & 3) == 0) {
                        float sl = Wl / Zl;
                        float sh = Wh / Zh;
                        denomAcc[2 * mf]     += __expf(LAMBDA_F * sl);
                        denomAcc[2 * mf + 1] += __expf(LAMBDA_F * sh);
                        int cg = chunk * 16 + warp_n * 4 + h * 2 + nf;   // global concept
                        if (cg == rl)     simPos[2 * mf]     = sl;       // k == row-in-CTA
                        if (cg == rl + 8) simPos[2 * mf + 1] = sh;
                    }
                }
            }
        }
    }

    // ---- per-row combine across warp_n via smem atomics ----
    __syncthreads();
    if ((lane & 3) == 0) {
        #pragma unroll
        for (int mf = 0; mf < 2; ++mf) {
            int r = warp_m * 32 + mf * 16 + (lane >> 2);
            atomicAdd(&denom_s[r],     denomAcc[2 * mf]);
            atomicAdd(&denom_s[r + 8], denomAcc[2 * mf + 1]);
            atomicAdd(&sims_s[r],      simPos[2 * mf]);
            atomicAdd(&sims_s[r + 8],  simPos[2 * mf + 1]);
        }
    }
    __syncthreads();

    float lsum = 0.0f;
    int   lcnt = 0;
    if (tid < BM) {
        float d = denom_s[tid];
        float p = sims_s[tid];
        float loss = logf(d + EPS_F) - LAMBDA_F * (p + MARGIN_F);
        if (labels[rowBase + tid] == 1) { lsum = loss; lcnt = 1; }
    }
    #pragma unroll
    for (int o = 16; o > 0; o >>= 1) {
        lsum += __shfl_xor_sync(0xffffffffu, lsum, o);
        lcnt += __shfl_xor_sync(0xffffffffu, lcnt, o);
    }
    __shared__ float ws[32];
    __shared__ int   wc[32];
    if (lane == 0) { ws[warp] = lsum; wc[warp] = lcnt; }
    __syncthreads();

    // ---- single-launch finalize: last CTA writes out, resets globals ----
    if (tid == 0) {
        float s = 0.0f; int n = 0;
        #pragma unroll
        for (int i = 0; i < 32; i++) { s += ws[i]; n += wc[i]; }
        atomicAdd(&g_loss_sum, s);
        atomicAdd(&g_pos_cnt, n);
        __threadfence();
        unsigned int old = atomicAdd(&g_done, 1u);
        if (old == NCTAS - 1) {
            float ts = g_loss_sum;
            int   tn = g_pos_cnt;
            out[0] = (tn > 0) ? (ts / (float)tn) : ts;
            g_loss_sum = 0.0f;
            g_pos_cnt  = 0;
            __threadfence();
            g_done = 0u;
        }
    }
}

extern "C" void kernel_launch(void* const* d_in, const int* in_sizes, int n_in,
                              void* d_out, int out_size)
{
    const float* V = nullptr;
    const int*   L = nullptr;
    const float* P = nullptr;
    for (int i = 0; i < n_in; i++) {
        if      (in_sizes[i] == NQ * D_SZ) V = (const float*)d_in[i];
        else if (in_sizes[i] == NQ)        L = (const int*)d_in[i];
        else if (in_sizes[i] == NP * D_SZ) P = (const float*)d_in[i];
    }

    cudaFuncSetAttribute(mpc_main_kernel,
                         cudaFuncAttributeMaxDynamicSharedMemorySize, SMEM_BYTES);

    mpc_main_kernel<<<NCTAS, NTHREADS, SMEM_BYTES>>>(V, L, P, (float*)d_out);
}

// round 6
// speedup vs baseline: 4.2613x; 1.6527x over previous
#include <cuda_runtime.h>
#include <cuda_fp16.h>
#include <math.h>
#include <stdint.h>

// ---------------- problem constants ----------------
#define B_SZ   128
#define K_SZ   256
#define M_SZ   8
#define D_SZ   128
#define NQ     (B_SZ * K_SZ)   // 32768 query rows
#define NP     (K_SZ * M_SZ)   // 2048 prototype rows

#define GAMMA_F  20.0f
#define LAMBDA_F 20.0f
#define MARGIN_F 0.05f
#define EPS_F    1e-8f

// ---------------- tile config ----------------
#define BM 256              // query rows per CTA (full K: k == row-in-CTA)
#define BN 128              // prototype rows per chunk (16 concepts)
#define NCHUNK (NP / BN)    // 16
#define NTHREADS 1024       // 32 warps: warp_m = w>>2 (8, 32 rows), warp_n = w&3 (4, 32 cols)
#define NCTAS (NQ / BM)     // 128

// padded fp16 tile row stride: 128 halves = 256B + 16B pad (conflict-free ldmatrix/STS)
#define TSTRIDE 272

#define OFF_A   0
#define OFF_B0  (BM * TSTRIDE)                    // 69632
#define OFF_B1  (OFF_B0 + BN * TSTRIDE)           // 104448
#define OFF_STG (OFF_B1 + BN * TSTRIDE)           // 139264 (raw fp32 B chunk, 64KB)
#define OFF_RED (OFF_STG + BN * D_SZ * 4)         // 204800
#define SMEM_BYTES (OFF_RED + 2 * BM * 4)         // 206848

__device__ float g_loss_sum;   // zero-init at load; reset by last CTA each call
__device__ int   g_pos_cnt;
__device__ unsigned int g_done;

__device__ __forceinline__ uint32_t smem_u32(const void* p) {
    uint32_t a;
    asm("{ .reg .u64 t; cvta.to.shared.u64 t, %1; cvt.u32.u64 %0, t; }" : "=r"(a) : "l"(p));
    return a;
}

__device__ __forceinline__ void ldsm_x4(uint32_t& r0, uint32_t& r1, uint32_t& r2, uint32_t& r3,
                                        uint32_t addr) {
    asm volatile("ldmatrix.sync.aligned.m8n8.x4.shared.b16 {%0,%1,%2,%3}, [%4];"
                 : "=r"(r0), "=r"(r1), "=r"(r2), "=r"(r3) : "r"(addr));
}

__device__ __forceinline__ void mma_f16(float* c, uint32_t a0, uint32_t a1, uint32_t a2,
                                        uint32_t a3, uint32_t b0, uint32_t b1) {
    asm volatile(
        "mma.sync.aligned.m16n8k16.row.col.f32.f16.f16.f32 "
        "{%0,%1,%2,%3}, {%4,%5,%6,%7}, {%8,%9}, {%0,%1,%2,%3};"
        : "+f"(c[0]), "+f"(c[1]), "+f"(c[2]), "+f"(c[3])
        : "r"(a0), "r"(a1), "r"(a2), "r"(a3), "r"(b0), "r"(b1));
}

__device__ __forceinline__ void cp_async16(uint32_t saddr, const void* gptr) {
    asm volatile("cp.async.cg.shared.global [%0], [%1], 16;" :: "r"(saddr), "l"(gptr));
}
#define CP_COMMIT() asm volatile("cp.async.commit_group;" ::: "memory")
#define CP_WAIT0()  asm volatile("cp.async.wait_group 0;" ::: "memory")

__device__ __forceinline__ uint32_t pack2h(float a, float b) {
    __half2 t = __floats2half2_rn(a, b);
    return *reinterpret_cast<uint32_t*>(&t);
}

// convert this thread's 4 staged fp32 float4s into fp16 tile rows
__device__ __forceinline__ void convert_stage(const char* stage, char* dst, int tid) {
    #pragma unroll
    for (int i = 0; i < 4; i++) {
        int linear = tid + i * NTHREADS;
        int row  = linear >> 5;
        int col4 = linear & 31;
        float4 v = *reinterpret_cast<const float4*>(stage + (size_t)linear * 16);
        *reinterpret_cast<uint2*>(dst + (uint32_t)row * TSTRIDE + (uint32_t)col4 * 8) =
            make_uint2(pack2h(v.x, v.y), pack2h(v.z, v.w));
    }
}

__device__ __forceinline__ void issue_stage(uint32_t stage_sb, const float* __restrict__ src,
                                            int tid) {
    #pragma unroll
    for (int i = 0; i < 4; i++) {
        int linear = tid + i * NTHREADS;
        cp_async16(stage_sb + (uint32_t)linear * 16,
                   reinterpret_cast<const float4*>(src) + linear);
    }
    CP_COMMIT();
}

__global__ __launch_bounds__(NTHREADS, 1)
void mpc_main_kernel(const float* __restrict__ V,
                     const int*   __restrict__ labels,
                     const float* __restrict__ P,
                     float* __restrict__ out)
{
    extern __shared__ char smem[];
    const uint32_t sb = smem_u32(smem);
    const int tid  = threadIdx.x;
    const int warp = tid >> 5;
    const int lane = tid & 31;
    const int warp_m = warp >> 2;   // 0..7 -> rows 32*warp_m
    const int warp_n = warp & 3;    // 0..3 -> cols 32*warp_n
    const int rowBase = blockIdx.x * BM;

    float* denom_s = reinterpret_cast<float*>(smem + OFF_RED);
    float* sims_s  = denom_s + BM;
    if (tid < BM) { denom_s[tid] = 0.0f; sims_s[tid] = 0.0f; }

    // ---- resident A tile (256 rows x 128), fp16, loaded once ----
    {
        const float4* gv = reinterpret_cast<const float4*>(V + (size_t)rowBase * D_SZ);
        #pragma unroll
        for (int i = 0; i < 8; i++) {
            int linear = tid + i * NTHREADS;
            int row  = linear >> 5;
            int col4 = linear & 31;
            float4 v = __ldg(gv + linear);
            *reinterpret_cast<uint2*>(smem + OFF_A + (uint32_t)row * TSTRIDE
                                      + (uint32_t)col4 * 8) =
                make_uint2(pack2h(v.x, v.y), pack2h(v.z, v.w));
        }
    }

    // ---- prologue: stage + convert chunk 0 into buf0 ----
    issue_stage(sb + OFF_STG, P, tid);
    CP_WAIT0();
    convert_stage(smem + OFF_STG, smem + OFF_B0, tid);
    __syncthreads();   // A + B0 visible to all

    // lane-invariant ldmatrix address components
    const uint32_t aLane = (uint32_t)(warp_m * 32 + (lane & 15)) * TSTRIDE
                         + (uint32_t)(lane >> 4) * 16;
    const uint32_t bLane = (uint32_t)(warp_n * 32 + ((lane >> 4) << 3) + (lane & 7)) * TSTRIDE
                         + (uint32_t)((lane >> 3) & 1) * 16;
    const uint32_t aB0 = sb + OFF_A + aLane;
    const uint32_t aB1 = aB0 + 16u * TSTRIDE;

    float denomAcc[4], simPos[4];   // [2*mf + lowhigh]
    #pragma unroll
    for (int i = 0; i < 4; i++) { denomAcc[i] = 0.0f; simPos[i] = 0.0f; }

    for (int chunk = 0; chunk < NCHUNK; ++chunk) {
        // prefetch next chunk's B into the fp32 stage (async, own lines only)
        if (chunk + 1 < NCHUNK)
            issue_stage(sb + OFF_STG, P + (size_t)((chunk + 1) * BN) * D_SZ, tid);

        const uint32_t bB0 = sb + ((chunk & 1) ? OFF_B1 : OFF_B0) + bLane;
        const uint32_t bB1 = bB0 + 16u * TSTRIDE;

        float acc[2][4][4];
        #pragma unroll
        for (int mf = 0; mf < 2; mf++)
            #pragma unroll
            for (int nf = 0; nf < 4; nf++)
                #pragma unroll
                for (int q = 0; q < 4; q++)
                    acc[mf][nf][q] = 0.0f;

        // single-pass fp16: per k-step 4 LDSM feed 8 MMAs
        #pragma unroll
        for (int ks = 0; ks < 8; ++ks) {
            const uint32_t ko = (uint32_t)ks * 32;
            uint32_t a0[4], a1[4];
            ldsm_x4(a0[0], a0[1], a0[2], a0[3], aB0 + ko);
            ldsm_x4(a1[0], a1[1], a1[2], a1[3], aB1 + ko);
            uint32_t b0, b1, b2, b3, b4, b5, b6, b7;
            ldsm_x4(b0, b1, b2, b3, bB0 + ko);   // cols 0-15: (b0,b1)=nf0, (b2,b3)=nf1
            ldsm_x4(b4, b5, b6, b7, bB1 + ko);   // cols 16-31: nf2, nf3

            mma_f16(acc[0][0], a0[0], a0[1], a0[2], a0[3], b0, b1);
            mma_f16(acc[0][1], a0[0], a0[1], a0[2], a0[3], b2, b3);
            mma_f16(acc[0][2], a0[0], a0[1], a0[2], a0[3], b4, b5);
            mma_f16(acc[0][3], a0[0], a0[1], a0[2], a0[3], b6, b7);
            mma_f16(acc[1][0], a1[0], a1[1], a1[2], a1[3], b0, b1);
            mma_f16(acc[1][1], a1[0], a1[1], a1[2], a1[3], b2, b3);
            mma_f16(acc[1][2], a1[0], a1[1], a1[2], a1[3], b4, b5);
            mma_f16(acc[1][3], a1[0], a1[1], a1[2], a1[3], b6, b7);
        }

        // ---- fused epilogue: quad spans one concept's 8 prototypes ----
        #pragma unroll
        for (int mf = 0; mf < 2; ++mf) {
            const int rl = warp_m * 32 + mf * 16 + (lane >> 2);   // low row (high = rl+8)
            #pragma unroll
            for (int nf = 0; nf < 4; ++nf) {
                float c0 = acc[mf][nf][0], c1 = acc[mf][nf][1];
                float c2 = acc[mf][nf][2], c3 = acc[mf][nf][3];
                float e0 = __expf(GAMMA_F * c0), e1 = __expf(GAMMA_F * c1);
                float e2 = __expf(GAMMA_F * c2), e3 = __expf(GAMMA_F * c3);
                float Zl = e0 + e1, Wl = fmaf(e0, c0, e1 * c1);
                float Zh = e2 + e3, Wh = fmaf(e2, c2, e3 * c3);
                #pragma unroll
                for (int o = 1; o <= 2; o <<= 1) {
                    Zl += __shfl_xor_sync(0xffffffffu, Zl, o);
                    Wl += __shfl_xor_sync(0xffffffffu, Wl, o);
                    Zh += __shfl_xor_sync(0xffffffffu, Zh, o);
                    Wh += __shfl_xor_sync(0xffffffffu, Wh, o);
                }
                if ((lane & 3) == 0) {
                    float sl = Wl / Zl;
                    float sh = Wh / Zh;
                    denomAcc[2 * mf]     += __expf(LAMBDA_F * sl);
                    denomAcc[2 * mf + 1] += __expf(LAMBDA_F * sh);
                    int cg = chunk * 16 + warp_n * 4 + nf;   // global concept
                    if (cg == rl)     simPos[2 * mf]     = sl;   // k == row-in-CTA
                    if (cg == rl + 8) simPos[2 * mf + 1] = sh;
                }
            }
        }

        // convert the prefetched chunk into the other buffer
        if (chunk + 1 < NCHUNK) {
            CP_WAIT0();
            convert_stage(smem + OFF_STG,
                          smem + ((chunk & 1) ? OFF_B0 : OFF_B1), tid);
        }
        __syncthreads();
    }

    // ---- per-row combine across warp_n via smem atomics ----
    if ((lane & 3) == 0) {
        #pragma unroll
        for (int mf = 0; mf < 2; ++mf) {
            int r = warp_m * 32 + mf * 16 + (lane >> 2);
            atomicAdd(&denom_s[r],     denomAcc[2 * mf]);
            atomicAdd(&denom_s[r + 8], denomAcc[2 * mf + 1]);
            atomicAdd(&sims_s[r],      simPos[2 * mf]);
            atomicAdd(&sims_s[r + 8],  simPos[2 * mf + 1]);
        }
    }
    __syncthreads();

    float lsum = 0.0f;
    int   lcnt = 0;
    if (tid < BM) {
        float d = denom_s[tid];
        float p = sims_s[tid];
        float loss = logf(d + EPS_F) - LAMBDA_F * (p + MARGIN_F);
        if (labels[rowBase + tid] == 1) { lsum = loss; lcnt = 1; }
    }
    #pragma unroll
    for (int o = 16; o > 0; o >>= 1) {
        lsum += __shfl_xor_sync(0xffffffffu, lsum, o);
        lcnt += __shfl_xor_sync(0xffffffffu, lcnt, o);
    }
    __shared__ float ws[32];
    __shared__ int   wc[32];
    if (lane == 0) { ws[warp] = lsum; wc[warp] = lcnt; }
    __syncthreads();

    // ---- single-launch finalize: last CTA writes out, resets globals ----
    if (tid == 0) {
        float s = 0.0f; int n = 0;
        #pragma unroll
        for (int i = 0; i < 32; i++) { s += ws[i]; n += wc[i]; }
        atomicAdd(&g_loss_sum, s);
        atomicAdd(&g_pos_cnt, n);
        __threadfence();
        unsigned int old = atomicAdd(&g_done, 1u);
        if (old == NCTAS - 1) {
            float ts = g_loss_sum;
            int   tn = g_pos_cnt;
            out[0] = (tn > 0) ? (ts / (float)tn) : ts;
            g_loss_sum = 0.0f;
            g_pos_cnt  = 0;
            __threadfence();
            g_done = 0u;
        }
    }
}

extern "C" void kernel_launch(void* const* d_in, const int* in_sizes, int n_in,
                              void* d_out, int out_size)
{
    const float* V = nullptr;
    const int*   L = nullptr;
    const float* P = nullptr;
    for (int i = 0; i < n_in; i++) {
        if      (in_sizes[i] == NQ * D_SZ) V = (const float*)d_in[i];
        else if (in_sizes[i] == NQ)        L = (const int*)d_in[i];
        else if (in_sizes[i] == NP * D_SZ) P = (const float*)d_in[i];
    }

    cudaFuncSetAttribute(mpc_main_kernel,
                         cudaFuncAttributeMaxDynamicSharedMemorySize, SMEM_BYTES);

    mpc_main_kernel<<<NCTAS, NTHREADS, SMEM_BYTES>>>(V, L, P, (float*)d_out);
}

// round 7
// speedup vs baseline: 4.7704x; 1.1195x over previous
#include <cuda_runtime.h>
#include <cuda_fp16.h>
#include <math.h>
#include <stdint.h>

// ---------------- problem constants ----------------
#define B_SZ   128
#define K_SZ   256
#define M_SZ   8
#define D_SZ   128
#define NQ     (B_SZ * K_SZ)   // 32768 query rows
#define NP     (K_SZ * M_SZ)   // 2048 prototype rows

#define GAMMA_F  20.0f
#define LAMBDA_F 20.0f
#define MARGIN_F 0.05f
#define EPS_F    1e-8f

// ---------------- tile config ----------------
#define BM 256              // query rows per CTA (full K: k == row-in-CTA)
#define BN 128              // prototype rows per chunk (16 concepts)
#define NCHUNK (NP / BN)    // 16
#define NTHREADS 1024       // 32 warps: warp_m = w>>2 (8, 32 rows), warp_n = w&3 (4, 32 cols)
#define NCTAS (NQ / BM)     // 128

// padded fp16 tile row stride: 128 halves = 256B + 16B pad (conflict-free ldmatrix/STS)
#define TSTRIDE 272

#define OFF_A   0
#define OFF_B0  (BM * TSTRIDE)                    // 69632
#define OFF_B1  (OFF_B0 + BN * TSTRIDE)           // 104448
#define OFF_STG (OFF_B1 + BN * TSTRIDE)           // 139264 (raw fp32 B chunk, 64KB)
#define OFF_RED (OFF_STG + BN * D_SZ * 4)         // 204800
#define SMEM_BYTES (OFF_RED + 2 * BM * 4)         // 206848

__device__ float g_loss_sum;   // zero-init at load; reset by last CTA each call
__device__ int   g_pos_cnt;
__device__ unsigned int g_done;

__device__ __forceinline__ uint32_t smem_u32(const void* p) {
    uint32_t a;
    asm("{ .reg .u64 t; cvta.to.shared.u64 t, %1; cvt.u32.u64 %0, t; }" : "=r"(a) : "l"(p));
    return a;
}

__device__ __forceinline__ void ldsm_x4(uint32_t& r0, uint32_t& r1, uint32_t& r2, uint32_t& r3,
                                        uint32_t addr) {
    asm volatile("ldmatrix.sync.aligned.m8n8.x4.shared.b16 {%0,%1,%2,%3}, [%4];"
                 : "=r"(r0), "=r"(r1), "=r"(r2), "=r"(r3) : "r"(addr));
}

__device__ __forceinline__ void mma_f16(float* c, uint32_t a0, uint32_t a1, uint32_t a2,
                                        uint32_t a3, uint32_t b0, uint32_t b1) {
    asm volatile(
        "mma.sync.aligned.m16n8k16.row.col.f32.f16.f16.f32 "
        "{%0,%1,%2,%3}, {%4,%5,%6,%7}, {%8,%9}, {%0,%1,%2,%3};"
        : "+f"(c[0]), "+f"(c[1]), "+f"(c[2]), "+f"(c[3])
        : "r"(a0), "r"(a1), "r"(a2), "r"(a3), "r"(b0), "r"(b1));
}

__device__ __forceinline__ void cp_async16(uint32_t saddr, const void* gptr) {
    asm volatile("cp.async.cg.shared.global [%0], [%1], 16;" :: "r"(saddr), "l"(gptr));
}
#define CP_COMMIT() asm volatile("cp.async.commit_group;" ::: "memory")
#define CP_WAIT0()  asm volatile("cp.async.wait_group 0;" ::: "memory")

__device__ __forceinline__ uint32_t pack2h(float a, float b) {
    __half2 t = __floats2half2_rn(a, b);
    return *reinterpret_cast<uint32_t*>(&t);
}

// convert this thread's 4 staged fp32 float4s into fp16 tile rows
// (strictly self-owned lines: same `linear` set this thread cp.async'd)
__device__ __forceinline__ void convert_stage(const char* stage, char* dst, int tid) {
    #pragma unroll
    for (int i = 0; i < 4; i++) {
        int linear = tid + i * NTHREADS;
        int row  = linear >> 5;
        int col4 = linear & 31;
        float4 v = *reinterpret_cast<const float4*>(stage + (size_t)linear * 16);
        *reinterpret_cast<uint2*>(dst + (uint32_t)row * TSTRIDE + (uint32_t)col4 * 8) =
            make_uint2(pack2h(v.x, v.y), pack2h(v.z, v.w));
    }
}

__device__ __forceinline__ void issue_stage(uint32_t stage_sb, const float* __restrict__ src,
                                            int tid) {
    #pragma unroll
    for (int i = 0; i < 4; i++) {
        int linear = tid + i * NTHREADS;
        cp_async16(stage_sb + (uint32_t)linear * 16,
                   reinterpret_cast<const float4*>(src) + linear);
    }
    CP_COMMIT();
}

__global__ __launch_bounds__(NTHREADS, 1)
void mpc_main_kernel(const float* __restrict__ V,
                     const int*   __restrict__ labels,
                     const float* __restrict__ P,
                     float* __restrict__ out)
{
    extern __shared__ char smem[];
    const uint32_t sb = smem_u32(smem);
    const int tid  = threadIdx.x;
    const int warp = tid >> 5;
    const int lane = tid & 31;
    const int warp_m = warp >> 2;   // 0..7 -> rows 32*warp_m
    const int warp_n = warp & 3;    // 0..3 -> cols 32*warp_n
    const int rowBase = blockIdx.x * BM;

    float* denom_s = reinterpret_cast<float*>(smem + OFF_RED);
    float* sims_s  = denom_s + BM;
    if (tid < BM) { denom_s[tid] = 0.0f; sims_s[tid] = 0.0f; }

    // ---- resident A tile (256 rows x 128), fp16, loaded once ----
    {
        const float4* gv = reinterpret_cast<const float4*>(V + (size_t)rowBase * D_SZ);
        #pragma unroll
        for (int i = 0; i < 8; i++) {
            int linear = tid + i * NTHREADS;
            int row  = linear >> 5;
            int col4 = linear & 31;
            float4 v = __ldg(gv + linear);
            *reinterpret_cast<uint2*>(smem + OFF_A + (uint32_t)row * TSTRIDE
                                      + (uint32_t)col4 * 8) =
                make_uint2(pack2h(v.x, v.y), pack2h(v.z, v.w));
        }
    }

    // ---- prologue: stage + convert chunk 0 into buf0 ----
    issue_stage(sb + OFF_STG, P, tid);
    CP_WAIT0();
    convert_stage(smem + OFF_STG, smem + OFF_B0, tid);
    __syncthreads();   // A + B0 visible to all

    // lane-invariant ldmatrix address components
    const uint32_t aLane = (uint32_t)(warp_m * 32 + (lane & 15)) * TSTRIDE
                         + (uint32_t)(lane >> 4) * 16;
    const uint32_t bLane = (uint32_t)(warp_n * 32 + ((lane >> 4) << 3) + (lane & 7)) * TSTRIDE
                         + (uint32_t)((lane >> 3) & 1) * 16;
    const uint32_t aB0 = sb + OFF_A + aLane;
    const uint32_t aB1 = aB0 + 16u * TSTRIDE;

    float denomAcc[4], simPos[4];   // [2*mf + lowhigh]
    #pragma unroll
    for (int i = 0; i < 4; i++) { denomAcc[i] = 0.0f; simPos[i] = 0.0f; }

    #pragma unroll 1
    for (int chunk = 0; chunk < NCHUNK; ++chunk) {
        // prefetch next chunk's B into the fp32 stage (async, self-owned lines)
        if (chunk + 1 < NCHUNK)
            issue_stage(sb + OFF_STG, P + (size_t)((chunk + 1) * BN) * D_SZ, tid);

        const uint32_t bB0 = sb + ((chunk & 1) ? OFF_B1 : OFF_B0) + bLane;
        const uint32_t bB1 = bB0 + 16u * TSTRIDE;

        float acc[2][4][4];
        #pragma unroll
        for (int mf = 0; mf < 2; mf++)
            #pragma unroll
            for (int nf = 0; nf < 4; nf++)
                #pragma unroll
                for (int q = 0; q < 4; q++)
                    acc[mf][nf][q] = 0.0f;

        // single-pass fp16: per k-step 4 LDSM feed 8 MMAs
        #pragma unroll
        for (int ks = 0; ks < 8; ++ks) {
            const uint32_t ko = (uint32_t)ks * 32;
            uint32_t a0[4], a1[4];
            ldsm_x4(a0[0], a0[1], a0[2], a0[3], aB0 + ko);
            ldsm_x4(a1[0], a1[1], a1[2], a1[3], aB1 + ko);
            uint32_t b0, b1, b2, b3, b4, b5, b6, b7;
            ldsm_x4(b0, b1, b2, b3, bB0 + ko);   // cols 0-15: (b0,b1)=nf0, (b2,b3)=nf1
            ldsm_x4(b4, b5, b6, b7, bB1 + ko);   // cols 16-31: nf2, nf3

            mma_f16(acc[0][0], a0[0], a0[1], a0[2], a0[3], b0, b1);
            mma_f16(acc[0][1], a0[0], a0[1], a0[2], a0[3], b2, b3);
            mma_f16(acc[0][2], a0[0], a0[1], a0[2], a0[3], b4, b5);
            mma_f16(acc[0][3], a0[0], a0[1], a0[2], a0[3], b6, b7);
            mma_f16(acc[1][0], a1[0], a1[1], a1[2], a1[3], b0, b1);
            mma_f16(acc[1][1], a1[0], a1[1], a1[2], a1[3], b2, b3);
            mma_f16(acc[1][2], a1[0], a1[1], a1[2], a1[3], b4, b5);
            mma_f16(acc[1][3], a1[0], a1[1], a1[2], a1[3], b6, b7);
        }

        // convert the prefetched chunk BEFORE the barrier; epilogue moves after it,
        // so epilogue(c) overlaps other warps' MMA(c+1) with no intervening barrier.
        if (chunk + 1 < NCHUNK) {
            CP_WAIT0();
            convert_stage(smem + OFF_STG,
                          smem + ((chunk & 1) ? OFF_B0 : OFF_B1), tid);
        }
        __syncthreads();

        // ---- fused epilogue: quad spans one concept's 8 prototypes ----
        #pragma unroll
        for (int mf = 0; mf < 2; ++mf) {
            const int rl = warp_m * 32 + mf * 16 + (lane >> 2);   // low row (high = rl+8)
            #pragma unroll
            for (int nf = 0; nf < 4; ++nf) {
                float c0 = acc[mf][nf][0], c1 = acc[mf][nf][1];
                float c2 = acc[mf][nf][2], c3 = acc[mf][nf][3];
                float e0 = __expf(GAMMA_F * c0), e1 = __expf(GAMMA_F * c1);
                float e2 = __expf(GAMMA_F * c2), e3 = __expf(GAMMA_F * c3);
                float Zl = e0 + e1, Wl = fmaf(e0, c0, e1 * c1);
                float Zh = e2 + e3, Wh = fmaf(e2, c2, e3 * c3);
                #pragma unroll
                for (int o = 1; o <= 2; o <<= 1) {
                    Zl += __shfl_xor_sync(0xffffffffu, Zl, o);
                    Wl += __shfl_xor_sync(0xffffffffu, Wl, o);
                    Zh += __shfl_xor_sync(0xffffffffu, Zh, o);
                    Wh += __shfl_xor_sync(0xffffffffu, Wh, o);
                }
                if ((lane & 3) == 0) {
                    float sl = __fdividef(Wl, Zl);
                    float sh = __fdividef(Wh, Zh);
                    denomAcc[2 * mf]     += __expf(LAMBDA_F * sl);
                    denomAcc[2 * mf + 1] += __expf(LAMBDA_F * sh);
                    int cg = chunk * 16 + warp_n * 4 + nf;   // global concept
                    if (cg == rl)     simPos[2 * mf]     = sl;   // k == row-in-CTA
                    if (cg == rl + 8) simPos[2 * mf + 1] = sh;
                }
            }
        }
    }

    // ---- per-row combine across warp_n via smem atomics ----
    __syncthreads();
    if ((lane & 3) == 0) {
        #pragma unroll
        for (int mf = 0; mf < 2; ++mf) {
            int r = warp_m * 32 + mf * 16 + (lane >> 2);
            atomicAdd(&denom_s[r],     denomAcc[2 * mf]);
            atomicAdd(&denom_s[r + 8], denomAcc[2 * mf + 1]);
            atomicAdd(&sims_s[r],      simPos[2 * mf]);
            atomicAdd(&sims_s[r + 8],  simPos[2 * mf + 1]);
        }
    }
    __syncthreads();

    float lsum = 0.0f;
    int   lcnt = 0;
    if (tid < BM) {
        float d = denom_s[tid];
        float p = sims_s[tid];
        float loss = __logf(d + EPS_F) - LAMBDA_F * (p + MARGIN_F);
        if (labels[rowBase + tid] == 1) { lsum = loss; lcnt = 1; }
    }
    #pragma unroll
    for (int o = 16; o > 0; o >>= 1) {
        lsum += __shfl_xor_sync(0xffffffffu, lsum, o);
        lcnt += __shfl_xor_sync(0xffffffffu, lcnt, o);
    }
    __shared__ float ws[32];
    __shared__ int   wc[32];
    if (lane == 0) { ws[warp] = lsum; wc[warp] = lcnt; }
    __syncthreads();

    // ---- single-launch finalize: last CTA writes out, resets globals ----
    if (tid == 0) {
        float s = 0.0f; int n = 0;
        #pragma unroll
        for (int i = 0; i < 32; i++) { s += ws[i]; n += wc[i]; }
        atomicAdd(&g_loss_sum, s);
        atomicAdd(&g_pos_cnt, n);
        __threadfence();
        unsigned int old = atomicAdd(&g_done, 1u);
        if (old == NCTAS - 1) {
            float ts = g_loss_sum;
            int   tn = g_pos_cnt;
            out[0] = (tn > 0) ? (ts / (float)tn) : ts;
            g_loss_sum = 0.0f;
            g_pos_cnt  = 0;
            __threadfence();
            g_done = 0u;
        }
    }
}

extern "C" void kernel_launch(void* const* d_in, const int* in_sizes, int n_in,
                              void* d_out, int out_size)
{
    const float* V = nullptr;
    const int*   L = nullptr;
    const float* P = nullptr;
    for (int i = 0; i < n_in; i++) {
        if      (in_sizes[i] == NQ * D_SZ) V = (const float*)d_in[i];
        else if (in_sizes[i] == NQ)        L = (const int*)d_in[i];
        else if (in_sizes[i] == NP * D_SZ) P = (const float*)d_in[i];
    }

    cudaFuncSetAttribute(mpc_main_kernel,
                         cudaFuncAttributeMaxDynamicSharedMemorySize, SMEM_BYTES);

    mpc_main_kernel<<<NCTAS, NTHREADS, SMEM_BYTES>>>(V, L, P, (float*)d_out);
}